// round 4
// baseline (speedup 1.0000x reference)
#include <cuda_runtime.h>

// Abbott STDP step, persistent fused kernel. D=8, B=2, N=2048.
// Out = concat(W_prev[B,N,N], W_new[B,N,N], xbar_pre_new[D,B,N], xbar_post_new[B,N])

#define DD 8
#define BB 2
#define NN 2048
#define ALPHA_P 0.95f
#define ALPHA_D 0.90f
#define PERSIST_GRID 296   // 2 blocks per SM on 148-SM sm_100a

static const long long N2  = (long long)NN * NN;       // 4,194,304
static const long long BN2 = (long long)BB * N2;       // 8,388,608
static const long long DBN = (long long)DD * BB * NN;  // 32,768
static const long long BN  = (long long)BB * NN;       // 4,096

// Persistent: each block loops over pre-neuron rows e (stride gridDim.x).
// 512 threads, one float4 of o per thread. Both batches accumulated in one
// sweep so dmap (134 MB) is read exactly once. Xpost/xbar_post are
// (b,o)-only -> hoisted out of the e-loop. All big tensors are read/written
// with streaming (.cs) hints since nothing is ever re-referenced.
__global__ __launch_bounds__(512, 2) void stdp_fused(
    const float* __restrict__ Xd,        // (D,B,N)
    const float* __restrict__ Xpost,     // (B,N)
    const float* __restrict__ xbar_pre,  // (D,B,N)
    const float* __restrict__ xbar_post, // (B,N)
    const float* __restrict__ W,         // (B,N,N)
    const float* __restrict__ dmap,      // (D,N,N)
    const float* __restrict__ A_p,       // (N,N)
    const float* __restrict__ A_d,       // (N,N)
    float* __restrict__ W_prev_out,
    float* __restrict__ W_new_out,
    float* __restrict__ pre_out,         // (D,B,N) or nullptr
    float* __restrict__ post_out)        // (B,N)   or nullptr
{
    const int o = threadIdx.x << 2;                 // 0..2044 step 4

    // Loop-invariant per-thread values: post-side spikes and traces.
    const float4 xpo0 = *(const float4*)(Xpost + o);
    const float4 xpo1 = *(const float4*)(Xpost + NN + o);
    const float4 xbp0 = *(const float4*)(xbar_post + o);
    const float4 xbp1 = *(const float4*)(xbar_post + NN + o);

    // post-trace output: tiny, write once from block 0.
    if (post_out && blockIdx.x == 0) {
        float4 pn0, pn1;
        pn0.x = fmaf(ALPHA_D, xbp0.x, (1.0f - ALPHA_D) * xpo0.x);
        pn0.y = fmaf(ALPHA_D, xbp0.y, (1.0f - ALPHA_D) * xpo0.y);
        pn0.z = fmaf(ALPHA_D, xbp0.z, (1.0f - ALPHA_D) * xpo0.z);
        pn0.w = fmaf(ALPHA_D, xbp0.w, (1.0f - ALPHA_D) * xpo0.w);
        pn1.x = fmaf(ALPHA_D, xbp1.x, (1.0f - ALPHA_D) * xpo1.x);
        pn1.y = fmaf(ALPHA_D, xbp1.y, (1.0f - ALPHA_D) * xpo1.y);
        pn1.z = fmaf(ALPHA_D, xbp1.z, (1.0f - ALPHA_D) * xpo1.z);
        pn1.w = fmaf(ALPHA_D, xbp1.w, (1.0f - ALPHA_D) * xpo1.w);
        *(float4*)(post_out + o) = pn0;
        *(float4*)(post_out + NN + o) = pn1;
    }

    __shared__ float s_pre[DD * BB];
    __shared__ float s_xd[DD * BB];

    for (int e = blockIdx.x; e < NN; e += gridDim.x) {
        __syncthreads();   // previous-iter smem readers done before overwrite
        if (threadIdx.x < DD * BB) {
            const size_t idx = (size_t)threadIdx.x * NN + e;  // (d*BB+b)*NN + e
            const float xp = xbar_pre[idx];
            const float xv = Xd[idx];
            s_pre[threadIdx.x] = xp;
            s_xd[threadIdx.x]  = xv;
            if (pre_out)
                pre_out[idx] = fmaf(ALPHA_P, xp, (1.0f - ALPHA_P) * xv);
        }
        __syncthreads();

        const size_t row = (size_t)e * NN + o;

        const float4 ap = __ldcs((const float4*)(A_p + row));
        const float4 ad = __ldcs((const float4*)(A_d + row));

        float4 sp0 = make_float4(0.f, 0.f, 0.f, 0.f);
        float4 sd0 = sp0, sp1 = sp0, sd1 = sp0;
#pragma unroll
        for (int d = 0; d < DD; d++) {
            const float4 dm = __ldcs((const float4*)(dmap + (size_t)d * N2 + row));
            const float p0 = s_pre[d * BB + 0];
            const float v0 = s_xd[d * BB + 0];
            const float p1 = s_pre[d * BB + 1];
            const float v1 = s_xd[d * BB + 1];
            sp0.x = fmaf(p0, dm.x, sp0.x); sp0.y = fmaf(p0, dm.y, sp0.y);
            sp0.z = fmaf(p0, dm.z, sp0.z); sp0.w = fmaf(p0, dm.w, sp0.w);
            sd0.x = fmaf(v0, dm.x, sd0.x); sd0.y = fmaf(v0, dm.y, sd0.y);
            sd0.z = fmaf(v0, dm.z, sd0.z); sd0.w = fmaf(v0, dm.w, sd0.w);
            sp1.x = fmaf(p1, dm.x, sp1.x); sp1.y = fmaf(p1, dm.y, sp1.y);
            sp1.z = fmaf(p1, dm.z, sp1.z); sp1.w = fmaf(p1, dm.w, sp1.w);
            sd1.x = fmaf(v1, dm.x, sd1.x); sd1.y = fmaf(v1, dm.y, sd1.y);
            sd1.z = fmaf(v1, dm.z, sd1.z); sd1.w = fmaf(v1, dm.w, sd1.w);
        }

        // batch 0 epilogue
        {
            const float4 w = __ldcs((const float4*)(W + row));
            float4 wn;
            wn.x = fminf(fmaxf(w.x + xpo0.x * sp0.x * ap.x - xbp0.x * sd0.x * ad.x, 0.f), 1.f);
            wn.y = fminf(fmaxf(w.y + xpo0.y * sp0.y * ap.y - xbp0.y * sd0.y * ad.y, 0.f), 1.f);
            wn.z = fminf(fmaxf(w.z + xpo0.z * sp0.z * ap.z - xbp0.z * sd0.z * ad.z, 0.f), 1.f);
            wn.w = fminf(fmaxf(w.w + xpo0.w * sp0.w * ap.w - xbp0.w * sd0.w * ad.w, 0.f), 1.f);
            __stcs((float4*)(W_prev_out + row), w);
            __stcs((float4*)(W_new_out  + row), wn);
        }
        // batch 1 epilogue
        {
            const size_t widx = (size_t)N2 + row;
            const float4 w = __ldcs((const float4*)(W + widx));
            float4 wn;
            wn.x = fminf(fmaxf(w.x + xpo1.x * sp1.x * ap.x - xbp1.x * sd1.x * ad.x, 0.f), 1.f);
            wn.y = fminf(fmaxf(w.y + xpo1.y * sp1.y * ap.y - xbp1.y * sd1.y * ad.y, 0.f), 1.f);
            wn.z = fminf(fmaxf(w.z + xpo1.z * sp1.z * ap.z - xbp1.z * sd1.z * ad.z, 0.f), 1.f);
            wn.w = fminf(fmaxf(w.w + xpo1.w * sp1.w * ap.w - xbp1.w * sd1.w * ad.w, 0.f), 1.f);
            __stcs((float4*)(W_prev_out + widx), w);
            __stcs((float4*)(W_new_out  + widx), wn);
        }
    }
}

// Fallback: output is only W_prev (straight copy of W).
__global__ void copy_w(const float* __restrict__ W, float* __restrict__ out, long long n)
{
    const long long i = (long long)blockIdx.x * blockDim.x + threadIdx.x;
    if (i * 4 < n) {
        *(float4*)(out + i * 4) = *(const float4*)(W + i * 4);
    }
}

extern "C" void kernel_launch(void* const* d_in, const int* in_sizes, int n_in,
                              void* d_out, int out_size)
{
    const float* Xd        = (const float*)d_in[0];
    const float* Xpost     = (const float*)d_in[1];
    const float* xbar_pre  = (const float*)d_in[2];
    const float* xbar_post = (const float*)d_in[3];
    const float* W         = (const float*)d_in[4];
    const float* dmap      = (const float*)d_in[5];
    const float* A_p       = (const float*)d_in[6];
    const float* A_d       = (const float*)d_in[7];

    float* out = (float*)d_out;
    const long long total = 2 * BN2 + DBN + BN;  // 16,814,080

    if ((long long)out_size >= total) {
        float* W_prev   = out;
        float* W_new    = out + BN2;
        float* pre_o    = out + 2 * BN2;
        float* post_o   = pre_o + DBN;
        stdp_fused<<<PERSIST_GRID, 512>>>(Xd, Xpost, xbar_pre, xbar_post, W, dmap,
                                          A_p, A_d, W_prev, W_new, pre_o, post_o);
    } else if ((long long)out_size >= 2 * BN2) {
        stdp_fused<<<PERSIST_GRID, 512>>>(Xd, Xpost, xbar_pre, xbar_post, W, dmap,
                                          A_p, A_d, out, out + BN2,
                                          (float*)nullptr, (float*)nullptr);
    } else {
        copy_w<<<(int)((BN2 / 4 + 255) / 256), 256>>>(W, out, BN2);
    }
}